// round 7
// baseline (speedup 1.0000x reference)
#include <cuda_runtime.h>
#include <cuda_fp16.h>
#include <cuda_bf16.h>
#include <cstdint>

// Inputs (metadata order):
//  d_in[0] charges             float32 [200000, 4]
//  d_in[1] cell                float32 [3, 3]        (unused)
//  d_in[2] positions           float32 [200000, 3]   (unused)
//  d_in[3] neighbor_indices    int32   [12800000, 2]
//  d_in[4] neighbor_distances  float32 [12800000]
//  d_out  potential            float32 [200000, 4]
//
// R7: hybrid gather paths. fp16 charges mirror lives BOTH in global (L2 path)
// and replicated across 8-CTA clusters' DSMEM (200KB/CTA x 8 = 1.6MB). 12 of
// 32 warps/SM gather via ld.shared::cluster (DSMEM fabric), 20 via L2 LDG.
// All REDs stay fp32 red.global.add.v4.f32 (L1tex/L2). Warps pull 256-edge
// chunks from a global atomic counter -> the DSMEM/L2 split self-balances;
// if DSMEM underperforms, L2 warps absorb the work at baseline rate.

#define N_ATOMS_C  200000
#define APC8       25000            // atoms per CTA (cluster of 8)
#define SMEM_BYTES (APC8 * 8)       // 200,000 B of fp16x4 rows
#define TPB_C      1024
#define CHUNK      256

__device__ uint2        g_ch_h[N_ATOMS_C];  // fp16x4 mirror of charges
__device__ unsigned int g_chunk_ctr;

__global__ void __launch_bounds__(256)
convert_charges_kernel(const float4* __restrict__ charges, int n_atoms) {
    int a = blockIdx.x * blockDim.x + threadIdx.x;
    if (a == 0) g_chunk_ctr = 0u;            // reset work counter each launch
    if (a >= n_atoms) return;
    float4 v = __ldg(&charges[a]);
    __half2 lo = __floats2half2_rn(v.x, v.y);
    __half2 hi = __floats2half2_rn(v.z, v.w);
    uint2 u;
    u.x = *reinterpret_cast<uint32_t*>(&lo);
    u.y = *reinterpret_cast<uint32_t*>(&hi);
    g_ch_h[a] = u;
}

__device__ __forceinline__ void red_add_v4(float4* p, float4 v) {
    asm volatile("red.global.add.v4.f32 [%0], {%1, %2, %3, %4};"
                 :: "l"(p), "f"(v.x), "f"(v.y), "f"(v.z), "f"(v.w)
                 : "memory");
}

__device__ __forceinline__ float4 h4_to_f4(uint32_t u0, uint32_t u1) {
    __half2 lo = *reinterpret_cast<__half2*>(&u0);
    __half2 hi = *reinterpret_cast<__half2*>(&u1);
    float2 a = __half22float2(lo);
    float2 b = __half22float2(hi);
    return make_float4(a.x, a.y, b.x, b.y);
}

// L2-path gather from the global fp16 mirror.
__device__ __forceinline__ float4 l2_gather(int idx) {
    uint32_t u0, u1;
    asm volatile("ld.global.nc.v2.b32 {%0, %1}, [%2];"
                 : "=r"(u0), "=r"(u1) : "l"(&g_ch_h[idx]));
    return h4_to_f4(u0, u1);
}

// DSMEM-path gather from the cluster-replicated mirror.
__device__ __forceinline__ float4 ds_gather(uint32_t sbase, int idx_s) {
    unsigned idx   = (unsigned)idx_s;
    unsigned rank  = idx / APC8;
    unsigned local = idx - rank * APC8;
    uint32_t addr  = sbase + local * 8u;
    uint32_t raddr;
    asm volatile("mapa.shared::cluster.u32 %0, %1, %2;"
                 : "=r"(raddr) : "r"(addr), "r"(rank));
    uint32_t u0, u1;
    asm volatile("ld.shared::cluster.v2.b32 {%0, %1}, [%2];"
                 : "=r"(u0), "=r"(u1) : "r"(raddr));
    return h4_to_f4(u0, u1);
}

__device__ __forceinline__ float4 scale4(float4 c, float w) {
    return make_float4(c.x * w, c.y * w, c.z * w, c.w * w);
}

__global__ void __launch_bounds__(TPB_C, 1)
hybrid_edge_kernel(const int2*  __restrict__ nbr,
                   const float* __restrict__ dist,
                   float4*      __restrict__ out,
                   int n_edges) {
    extern __shared__ uint2 sch[];   // this CTA's 25000-atom slice (fp16x4)

    unsigned rank;
    asm("mov.u32 %0, %%cluster_ctarank;" : "=r"(rank));

    int base_atom = (int)rank * APC8;
    for (int a = threadIdx.x; a < APC8; a += TPB_C)
        sch[a] = g_ch_h[base_atom + a];

    asm volatile("barrier.cluster.arrive.aligned;" ::: "memory");
    asm volatile("barrier.cluster.wait.aligned;"   ::: "memory");

    uint32_t sbase;
    asm("{ .reg .u64 t; cvta.to.shared.u64 t, %1; cvt.u32.u64 %0, t; }"
        : "=r"(sbase) : "l"(sch));

    int  lane   = threadIdx.x & 31;
    int  wid_g  = blockIdx.x * (TPB_C / 32) + (threadIdx.x >> 5);
    bool use_ds = ((wid_g & 7) < 3);   // 12 of 32 warps per SM use DSMEM

    for (;;) {
        unsigned c;
        if (lane == 0) c = atomicAdd(&g_chunk_ctr, 1u);
        c = __shfl_sync(0xffffffffu, c, 0);
        int b = (int)(c * CHUNK);
        if (b >= n_edges) break;
        int e_end = b + CHUNK;
        if (e_end > n_edges) e_end = n_edges;

        for (int e = b + lane; e < e_end; e += 32) {
            int2  ij = __ldcs(&nbr[e]);
            float w  = 0.5f / __ldcs(&dist[e]);
            float4 cj, ci;
            if (use_ds) {
                cj = ds_gather(sbase, ij.y);
                ci = ds_gather(sbase, ij.x);
            } else {
                cj = l2_gather(ij.y);
                ci = l2_gather(ij.x);
            }
            red_add_v4(&out[ij.x], scale4(cj, w));
            red_add_v4(&out[ij.y], scale4(ci, w));
        }
    }

    // No CTA may exit while peers might still read its smem.
    asm volatile("barrier.cluster.arrive.aligned;" ::: "memory");
    asm volatile("barrier.cluster.wait.aligned;"   ::: "memory");
}

// Fallback: plain fp16-mirror kernel (measured ~192us).
__global__ void __launch_bounds__(256)
edge_scatter_kernel(const int2*  __restrict__ nbr,
                    const float* __restrict__ dist,
                    float4*      __restrict__ out,
                    int n_edges) {
    int e = blockIdx.x * blockDim.x + threadIdx.x;
    if (e >= n_edges) return;
    int2  ij = __ldcs(&nbr[e]);
    float w  = 0.5f / __ldcs(&dist[e]);
    float4 cj = l2_gather(ij.y);
    float4 ci = l2_gather(ij.x);
    red_add_v4(&out[ij.x], scale4(cj, w));
    red_add_v4(&out[ij.y], scale4(ci, w));
}

extern "C" void kernel_launch(void* const* d_in, const int* in_sizes, int n_in,
                              void* d_out, int out_size) {
    const float4* charges = (const float4*)d_in[0];
    const int2*   nbr     = (const int2*)d_in[3];
    const float*  dist    = (const float*)d_in[4];
    float4*       out     = (float4*)d_out;

    int n_edges = in_sizes[4];        // 12,800,000
    int n_atoms = in_sizes[0] / 4;    // 200,000

    cudaMemsetAsync(d_out, 0, (size_t)out_size * sizeof(float));

    const int TPB = 256;
    int cblocks = (n_atoms + TPB - 1) / TPB;
    convert_charges_kernel<<<cblocks, TPB>>>(charges, n_atoms);

    bool ok = (n_atoms == N_ATOMS_C);
    if (ok) {
        cudaFuncSetAttribute(hybrid_edge_kernel,
                             cudaFuncAttributeMaxDynamicSharedMemorySize, SMEM_BYTES);

        cudaLaunchConfig_t cfg = {};
        cfg.blockDim = dim3(TPB_C, 1, 1);
        cfg.dynamicSmemBytes = SMEM_BYTES;
        cfg.stream = 0;
        cudaLaunchAttribute at[1];
        at[0].id = cudaLaunchAttributeClusterDimension;
        at[0].val.clusterDim.x = 8;
        at[0].val.clusterDim.y = 1;
        at[0].val.clusterDim.z = 1;
        cfg.attrs = at;
        cfg.numAttrs = 1;

        int n_clusters = 0;
        cfg.gridDim = dim3(8, 1, 1);
        cudaError_t qerr = cudaOccupancyMaxActiveClusters(&n_clusters,
                                                          hybrid_edge_kernel, &cfg);
        if (qerr != cudaSuccess || n_clusters < 1) { n_clusters = 18; cudaGetLastError(); }

        cfg.gridDim = dim3(n_clusters * 8, 1, 1);
        cudaError_t err = cudaLaunchKernelEx(&cfg, hybrid_edge_kernel,
                                             nbr, dist, out, n_edges);
        if (err != cudaSuccess) { cudaGetLastError(); ok = false; }
    }

    if (!ok) {
        int blocks = (n_edges + TPB - 1) / TPB;
        edge_scatter_kernel<<<blocks, TPB>>>(nbr, dist, out, n_edges);
    }
}

// round 8
// speedup vs baseline: 1.6575x; 1.6575x over previous
#include <cuda_runtime.h>
#include <cuda_bf16.h>

// Inputs (metadata order):
//  d_in[0] charges             float32 [200000, 4]
//  d_in[1] cell                float32 [3, 3]        (unused)
//  d_in[2] positions           float32 [200000, 3]   (unused)
//  d_in[3] neighbor_indices    int32   [12800000, 2]
//  d_in[4] neighbor_distances  float32 [12800000]
//  d_out  potential            float32 [200000, 4]
//
// out[i] += 0.5/d * charges[j];  out[j] += 0.5/d * charges[i]  over all edges.
//
// R8 (final): R1 shape — 1 edge/thread, fp32 gathers, red.global.add.v4.f32.
// This kernel runs at 1.01 L1tex wavefronts/cyc/SM, i.e. at the hardware
// floor for 4 scattered 16B ops/edge. Confirmed by: fp16 mirror (neutral,
// wavefronts count lines not bytes), cache-policy pinning (neutral), DSMEM
// cluster replication (1.7-2.2x WORSE), and analytic pricing of TMA-gather,
// sort-then-coalesce, and smem privatization (all above 190us).

__device__ __forceinline__ void red_add_v4(float4* p, float4 v) {
    asm volatile("red.global.add.v4.f32 [%0], {%1, %2, %3, %4};"
                 :: "l"(p), "f"(v.x), "f"(v.y), "f"(v.z), "f"(v.w)
                 : "memory");
}

__device__ __forceinline__ float4 scale4(float4 c, float w) {
    return make_float4(c.x * w, c.y * w, c.z * w, c.w * w);
}

__global__ void __launch_bounds__(256)
edge_scatter_kernel(const float4* __restrict__ charges,
                    const int2*   __restrict__ nbr,
                    const float*  __restrict__ dist,
                    float4*       __restrict__ out,
                    int n_edges) {
    int e = blockIdx.x * blockDim.x + threadIdx.x;
    if (e >= n_edges) return;

    int2  ij  = __ldg(&nbr[e]);
    float d   = __ldg(&dist[e]);
    float inv = 0.5f / d;   // fold PREFACTOR * 0.5

    float4 cj = __ldg(&charges[ij.y]);
    float4 ci = __ldg(&charges[ij.x]);

    red_add_v4(&out[ij.x], scale4(cj, inv));
    red_add_v4(&out[ij.y], scale4(ci, inv));
}

extern "C" void kernel_launch(void* const* d_in, const int* in_sizes, int n_in,
                              void* d_out, int out_size) {
    const float4* charges = (const float4*)d_in[0];
    const int2*   nbr     = (const int2*)d_in[3];
    const float*  dist    = (const float*)d_in[4];
    float4*       out     = (float4*)d_out;

    int n_edges = in_sizes[4];   // 12,800,000

    // d_out is poisoned to 0xAA — zero it (async, graph-capturable).
    cudaMemsetAsync(d_out, 0, (size_t)out_size * sizeof(float));

    const int TPB = 256;
    int blocks = (n_edges + TPB - 1) / TPB;
    edge_scatter_kernel<<<blocks, TPB>>>(charges, nbr, dist, out, n_edges);
}

// round 9
// speedup vs baseline: 1.6667x; 1.0055x over previous
#include <cuda_runtime.h>
#include <cuda_bf16.h>

// Inputs (metadata order):
//  d_in[0] charges             float32 [200000, 4]
//  d_in[1] cell                float32 [3, 3]        (unused)
//  d_in[2] positions           float32 [200000, 3]   (unused)
//  d_in[3] neighbor_indices    int32   [12800000, 2]
//  d_in[4] neighbor_distances  float32 [12800000]
//  d_out  potential            float32 [200000, 4]
//
// out[i] += 0.5/d * charges[j];  out[j] += 0.5/d * charges[i]  over all edges.
//
// R9 (final geometry probe): proven optimal shape — 1 edge/thread, fp32
// gathers, red.global.add.v4.f32 — at TPB=512. This kernel runs at the
// hardware floor: 4 scattered 16B L1tex wavefronts per edge, retired at the
// measured 1.0 wf/cyc/SM rate (~190us). Falsified alternatives: fp16 mirror
// (neutral; wavefronts count lines, not bytes), cache-policy pinning
// (neutral), DSMEM cluster gathers (1.7-2.2x worse, twice), TMA gather
// (~480us analytic), sort/bin + coalesce (sort cost exceeds savings), smem
// privatization (ATOMS 2 cyc/lane > 1 wf/cyc).

__device__ __forceinline__ void red_add_v4(float4* p, float4 v) {
    asm volatile("red.global.add.v4.f32 [%0], {%1, %2, %3, %4};"
                 :: "l"(p), "f"(v.x), "f"(v.y), "f"(v.z), "f"(v.w)
                 : "memory");
}

__device__ __forceinline__ float4 scale4(float4 c, float w) {
    return make_float4(c.x * w, c.y * w, c.z * w, c.w * w);
}

__global__ void __launch_bounds__(512)
edge_scatter_kernel(const float4* __restrict__ charges,
                    const int2*   __restrict__ nbr,
                    const float*  __restrict__ dist,
                    float4*       __restrict__ out,
                    int n_edges) {
    int e = blockIdx.x * blockDim.x + threadIdx.x;
    if (e >= n_edges) return;

    int2  ij  = __ldg(&nbr[e]);
    float d   = __ldg(&dist[e]);
    float inv = 0.5f / d;   // fold PREFACTOR * 0.5

    float4 cj = __ldg(&charges[ij.y]);
    float4 ci = __ldg(&charges[ij.x]);

    red_add_v4(&out[ij.x], scale4(cj, inv));
    red_add_v4(&out[ij.y], scale4(ci, inv));
}

extern "C" void kernel_launch(void* const* d_in, const int* in_sizes, int n_in,
                              void* d_out, int out_size) {
    const float4* charges = (const float4*)d_in[0];
    const int2*   nbr     = (const int2*)d_in[3];
    const float*  dist    = (const float*)d_in[4];
    float4*       out     = (float4*)d_out;

    int n_edges = in_sizes[4];   // 12,800,000

    // d_out is poisoned to 0xAA — zero it (async, graph-capturable).
    cudaMemsetAsync(d_out, 0, (size_t)out_size * sizeof(float));

    const int TPB = 512;
    int blocks = (n_edges + TPB - 1) / TPB;
    edge_scatter_kernel<<<blocks, TPB>>>(charges, nbr, dist, out, n_edges);
}